// round 15
// baseline (speedup 1.0000x reference)
#include <cuda_runtime.h>
#include <cuda_bf16.h>
#include <mma.h>
#include <math.h>

using namespace nvcuda;

#define SEQ   4096
#define BATCH 8
#define MD    4
#define ORDER 256
#define INPUT 256
#define HID   512
#define MSZ   1280
#define NH    4096      // complex FFT size (= 8192/2), real-FFT packing
#define LOGH  12
#define KS    4224      // spectrum row stride (33*128)
#define FFT_T 512

// padded smem index map: +1 word every 16 -> conflict-free radix-16 passes.
#define PH(i) ((i) + ((i) >> 4))
#define SMSZ  4352

typedef wmma::fragment<wmma::matrix_a, 16, 16, 16, __nv_bfloat16, wmma::row_major> FA;
typedef wmma::fragment<wmma::matrix_b, 16, 16, 16, __nv_bfloat16, wmma::row_major> FBr;
typedef wmma::fragment<wmma::matrix_b, 16, 16, 16, __nv_bfloat16, wmma::col_major> FBc;
typedef wmma::fragment<wmma::accumulator, 16, 16, 16, float> FC;

// ---------------- scratch (static device globals; no allocation) -----------------
__device__ float  g_u  [32 * SEQ];
__device__ float2 g_tw [NH];            // e^{-2*pi*i*k/8192}
__device__ float  g_Ure[32 * KS];
__device__ float  g_Uim[32 * KS];
__device__ __nv_bfloat16 g_Hrehi[ORDER * KS];
__device__ __nv_bfloat16 g_Hrelo[ORDER * KS];
__device__ __nv_bfloat16 g_Himhi[ORDER * KS];
__device__ __nv_bfloat16 g_Himlo[ORDER * KS];
__device__ __nv_bfloat16 g_Whi[HID * MSZ];
__device__ __nv_bfloat16 g_Wlo[HID * MSZ];
__device__ __nv_bfloat16 g_xhi[BATCH * SEQ * INPUT];
__device__ __nv_bfloat16 g_xlo[BATCH * SEQ * INPUT];
__device__ float  g_Gre[HID * MD * KS];
__device__ float  g_Gim[HID * MD * KS];
__device__ float  g_hx [BATCH * HID * SEQ];  // h (pre-relu then relu'd), [b][h][t]

__device__ __forceinline__ int rev12(int x) { return (int)(__brev((unsigned)x) >> 20); }

__device__ __forceinline__ void bsplit(float v, __nv_bfloat16& hi, __nv_bfloat16& lo) {
    hi = __float2bfloat16(v);
    lo = __float2bfloat16(v - __bfloat162float(hi));
}

// 16-byte async copy global -> shared (LDGSTS)
__device__ __forceinline__ void cp16(void* smem, const void* gmem) {
    unsigned sa = (unsigned)__cvta_generic_to_shared(smem);
    asm volatile("cp.async.cg.shared.global [%0], [%1], 16;" :: "r"(sa), "l"(gmem));
}
__device__ __forceinline__ void cp_commit() { asm volatile("cp.async.commit_group;"); }

// 4 radix-2 DIT stages (conj twiddles) on 16 register-resident points.
template<int SHIFT>
__device__ __forceinline__ void fft16_dit(float* vr_, float* vi_, int jbase, int stride) {
    #pragma unroll
    for (int ss = 0; ss < 4; ++ss) {
        int mloc = 1 << ss;
        #pragma unroll
        for (int u = 0; u < 8; ++u) {
            int t0 = ((u >> ss) << (ss + 1)) | (u & (mloc - 1));
            int t1 = t0 + mloc;
            int jg = jbase + stride * (u & (mloc - 1));
            float2 w = g_tw[jg << (SHIFT - ss)];
            float br = vr_[t1], bi = vi_[t1];
            float pr = br * w.x + bi * w.y;
            float pi = bi * w.x - br * w.y;
            float ar = vr_[t0], ai = vi_[t0];
            vr_[t0] = ar + pr;  vi_[t0] = ai + pi;
            vr_[t1] = ar - pr;  vi_[t1] = ai - pi;
        }
    }
}

// ---------------- setup: twiddle table + Wh hi/lo split (one launch) -----------------
__global__ void setup_kernel(const float* __restrict__ Wh_w) {
    int i = blockIdx.x * blockDim.x + threadIdx.x;
    if (i < NH) {
        float s, c;
        sincospif(-(float)i / 4096.0f, &s, &c);
        g_tw[i] = make_float2(c, s);
    }
    if (i < HID * MSZ) bsplit(Wh_w[i], g_Whi[i], g_Wlo[i]);
}

// ---------------- u = relu(x @ Wu^T + b), fused x hi/lo split -------------------------
__global__ void u_kernel(const float* __restrict__ x,
                         const float* __restrict__ Wu_w,
                         const float* __restrict__ Wu_b) {
    int gw   = (blockIdx.x * blockDim.x + threadIdx.x) >> 5;
    int lane = threadIdx.x & 31;
    if (gw >= BATCH * SEQ) return;
    int b = gw >> 12, t = gw & (SEQ - 1);
    size_t rowoff = (size_t)(b * SEQ + t) * INPUT;
    const float* xp = x + rowoff;
    float a0 = 0.f, a1 = 0.f, a2 = 0.f, a3 = 0.f;
    #pragma unroll
    for (int i = lane; i < INPUT; i += 32) {
        float xv = xp[i];
        __nv_bfloat16 hi, lo;
        bsplit(xv, hi, lo);
        g_xhi[rowoff + i] = hi;
        g_xlo[rowoff + i] = lo;
        a0 = fmaf(xv, __ldg(&Wu_w[0 * INPUT + i]), a0);
        a1 = fmaf(xv, __ldg(&Wu_w[1 * INPUT + i]), a1);
        a2 = fmaf(xv, __ldg(&Wu_w[2 * INPUT + i]), a2);
        a3 = fmaf(xv, __ldg(&Wu_w[3 * INPUT + i]), a3);
    }
    #pragma unroll
    for (int off = 16; off; off >>= 1) {
        a0 += __shfl_down_sync(0xffffffffu, a0, off);
        a1 += __shfl_down_sync(0xffffffffu, a1, off);
        a2 += __shfl_down_sync(0xffffffffu, a2, off);
        a3 += __shfl_down_sync(0xffffffffu, a3, off);
    }
    if (lane == 0) {
        g_u[(b * 4 + 0) * SEQ + t] = fmaxf(a0 + Wu_b[0], 0.f);
        g_u[(b * 4 + 1) * SEQ + t] = fmaxf(a1 + Wu_b[1], 0.f);
        g_u[(b * 4 + 2) * SEQ + t] = fmaxf(a2 + Wu_b[2], 0.f);
        g_u[(b * 4 + 3) * SEQ + t] = fmaxf(a3 + Wu_b[3], 0.f);
    }
}

// ---------------- forward real FFT, both inputs in ONE launch -------------------------
__global__ void fft_fwd_kernel(const float* __restrict__ Hin) {
    __shared__ float sre[NH];
    __shared__ float sim[NH];
    int blk = blockIdx.x;
    int mode = (blk >= 32);
    int row = mode ? (blk - 32) : blk;
    int tid = threadIdx.x;
    const float* in = mode ? (Hin + (size_t)row * SEQ) : (g_u + (size_t)row * SEQ);

    const float2* in2 = (const float2*)in;
    #pragma unroll
    for (int r = 0; r < NH / FFT_T; ++r) {
        int n = tid + r * FFT_T;
        if (n < SEQ / 2) { float2 v = in2[n]; sre[n] = v.x; sim[n] = v.y; }
        else             { sre[n] = 0.f;      sim[n] = 0.f; }
    }
    __syncthreads();

    #pragma unroll
    for (int s = LOGH - 2; s >= 0; s -= 2) {
        int m = 1 << s;
        #pragma unroll
        for (int r = 0; r < (NH / 4) / FFT_T; ++r) {
            int k = tid + r * FFT_T;
            int j = k & (m - 1);
            int base = ((k >> s) << (s + 2)) + j;
            int ia = base, ib = base + m, ic = base + 2 * m, id = base + 3 * m;
            float2 w2 = g_tw[j << (LOGH - s - 1)];
            float2 w1 = g_tw[j << (LOGH - s)];
            float ar = sre[ia], ai = sim[ia];
            float br = sre[ib], bi = sim[ib];
            float cr = sre[ic], ci = sim[ic];
            float dr = sre[id], di = sim[id];
            float a1r = ar + cr, a1i = ai + ci;
            float tr  = ar - cr, ti  = ai - ci;
            float c1r = tr * w2.x - ti * w2.y;
            float c1i = tr * w2.y + ti * w2.x;
            float b1r = br + dr, b1i = bi + di;
            tr = br - dr; ti = bi - di;
            float er = tr * w2.x - ti * w2.y;
            float ei = tr * w2.y + ti * w2.x;
            float d1r = ei, d1i = -er;                     // * (-i)
            sre[ia] = a1r + b1r;  sim[ia] = a1i + b1i;
            tr = a1r - b1r; ti = a1i - b1i;
            sre[ib] = tr * w1.x - ti * w1.y;
            sim[ib] = tr * w1.y + ti * w1.x;
            sre[ic] = c1r + d1r;  sim[ic] = c1i + d1i;
            tr = c1r - d1r; ti = c1i - d1i;
            sre[id] = tr * w1.x - ti * w1.y;
            sim[id] = tr * w1.y + ti * w1.x;
        }
        __syncthreads();
    }

    if (mode == 0) {
        float* outre = g_Ure + (size_t)row * KS;
        float* outim = g_Uim + (size_t)row * KS;
        #pragma unroll
        for (int r = 0; r < NH / FFT_T; ++r) {
            int j = tid + r * FFT_T;
            if (j == 0) {
                float zr = sre[0], zi = sim[0];
                outre[0]  = zr + zi;  outim[0]  = 0.f;
                outre[NH] = zr - zi;  outim[NH] = 0.f;
            } else {
                int k = rev12(j);
                int p = rev12(NH - k);
                float zjr = sre[j], zji = sim[j];
                float zpr = sre[p], zpi = sim[p];
                float Ar = 0.5f * (zjr + zpr), Ai = 0.5f * (zji - zpi);
                float Br = 0.5f * (zji + zpi), Bi = -0.5f * (zjr - zpr);
                float2 w = g_tw[k];
                outre[j] = Ar + w.x * Br - w.y * Bi;
                outim[j] = Ai + w.x * Bi + w.y * Br;
            }
        }
    } else {
        size_t off = (size_t)row * KS;
        for (int pcol = NH + 1 + tid; pcol < KS; pcol += FFT_T) {
            g_Hrehi[off + pcol] = __float2bfloat16(0.f);
            g_Hrelo[off + pcol] = __float2bfloat16(0.f);
            g_Himhi[off + pcol] = __float2bfloat16(0.f);
            g_Himlo[off + pcol] = __float2bfloat16(0.f);
        }
        #pragma unroll
        for (int r = 0; r < NH / FFT_T; ++r) {
            int j = tid + r * FFT_T;
            float vre, vim;
            if (j == 0) {
                float zr = sre[0], zi = sim[0];
                vre = zr + zi; vim = 0.f;
                float nre = zr - zi;
                bsplit(nre, g_Hrehi[off + NH], g_Hrelo[off + NH]);
                bsplit(0.f, g_Himhi[off + NH], g_Himlo[off + NH]);
            } else {
                int k = rev12(j);
                int p = rev12(NH - k);
                float zjr = sre[j], zji = sim[j];
                float zpr = sre[p], zpi = sim[p];
                float Ar = 0.5f * (zjr + zpr), Ai = 0.5f * (zji - zpi);
                float Br = 0.5f * (zji + zpi), Bi = -0.5f * (zjr - zpr);
                float2 w = g_tw[k];
                vre = Ar + w.x * Br - w.y * Bi;
                vim = Ai + w.x * Bi + w.y * Br;
            }
            bsplit(vre, g_Hrehi[off + j], g_Hrelo[off + j]);
            bsplit(vim, g_Himhi[off + j], g_Himlo[off + j]);
        }
    }
}

// ---------------- G build: re/im-split, cp.async double-buffered --------------------
// gridDim.z = MD*2: z = d*2 + reim. Each block computes only real or imag G.
struct GBuf {
    __nv_bfloat16 Ahi[64][40], Alo[64][40];    // [m][k]
    __nv_bfloat16 Bhi[32][136], Blo[32][136];  // [k][n] (one of re/im)
};
#define GB_SMEM ((int)(2 * sizeof(GBuf)))

__device__ __forceinline__ void gbuild_load(GBuf& bb, const __nv_bfloat16* __restrict__ Hhi,
                                            const __nv_bfloat16* __restrict__ Hlo,
                                            int d, int h0, int k0, int o0, int tid) {
    {
        int m = tid >> 2, c = (tid & 3) * 8;
        size_t src = (size_t)(h0 + m) * MSZ + d * ORDER + o0 + c;
        cp16(&bb.Ahi[m][c], &g_Whi[src]);
        cp16(&bb.Alo[m][c], &g_Wlo[src]);
    }
    #pragma unroll
    for (int r = 0; r < 2; ++r) {
        int oo = (tid >> 4) + r * 16;
        int c  = (tid & 15) * 8;
        size_t src = (size_t)(o0 + oo) * KS + k0 + c;
        cp16(&bb.Bhi[oo][c], &Hhi[src]);
        cp16(&bb.Blo[oo][c], &Hlo[src]);
    }
}

__global__ __launch_bounds__(256, 2)
void gbuild_bf16_kernel() {
    extern __shared__ char smem_raw[];
    GBuf* bufs = (GBuf*)smem_raw;
    int zz   = blockIdx.z;
    int reim = zz & 1;
    int d    = zz >> 1;
    int h0 = blockIdx.y * 64;
    int k0 = blockIdx.x * 128;
    int tid = threadIdx.x;
    int w  = tid >> 5;
    int wm = w & 1;
    int wn = w >> 1;

    const __nv_bfloat16* Hhi = reim ? g_Himhi : g_Hrehi;
    const __nv_bfloat16* Hlo = reim ? g_Himlo : g_Hrelo;
    float* Gdst = reim ? g_Gim : g_Gre;

    FC acc[2][2];
    #pragma unroll
    for (int m2 = 0; m2 < 2; ++m2)
        #pragma unroll
        for (int n2 = 0; n2 < 2; ++n2)
            wmma::fill_fragment(acc[m2][n2], 0.f);

    gbuild_load(bufs[0], Hhi, Hlo, d, h0, k0, 0, tid);
    cp_commit();

    #pragma unroll
    for (int it = 0; it < ORDER / 32; ++it) {
        int cur = it & 1;
        if (it + 1 < ORDER / 32) {
            gbuild_load(bufs[cur ^ 1], Hhi, Hlo, d, h0, k0, (it + 1) * 32, tid);
            cp_commit();
            asm volatile("cp.async.wait_group 1;");
        } else {
            asm volatile("cp.async.wait_group 0;");
        }
        __syncthreads();
        GBuf& bb = bufs[cur];
        #pragma unroll
        for (int kk = 0; kk < 32; kk += 16) {
            FA ahi[2], alo[2];
            #pragma unroll
            for (int m2 = 0; m2 < 2; ++m2) {
                wmma::load_matrix_sync(ahi[m2], &bb.Ahi[wm * 32 + m2 * 16][kk], 40);
                wmma::load_matrix_sync(alo[m2], &bb.Alo[wm * 32 + m2 * 16][kk], 40);
            }
            #pragma unroll
            for (int n2 = 0; n2 < 2; ++n2) {
                FBr bhi, blo;
                wmma::load_matrix_sync(bhi, &bb.Bhi[kk][wn * 32 + n2 * 16], 136);
                wmma::load_matrix_sync(blo, &bb.Blo[kk][wn * 32 + n2 * 16], 136);
                #pragma unroll
                for (int m2 = 0; m2 < 2; ++m2) {
                    wmma::mma_sync(acc[m2][n2], ahi[m2], bhi, acc[m2][n2]);
                    wmma::mma_sync(acc[m2][n2], alo[m2], bhi, acc[m2][n2]);
                    wmma::mma_sync(acc[m2][n2], ahi[m2], blo, acc[m2][n2]);
                }
            }
        }
        __syncthreads();
    }
    #pragma unroll
    for (int m2 = 0; m2 < 2; ++m2)
        #pragma unroll
        for (int n2 = 0; n2 < 2; ++n2) {
            size_t dst = ((size_t)(h0 + wm * 32 + m2 * 16) * MD + d) * KS
                       + k0 + wn * 32 + n2 * 16;
            wmma::store_matrix_sync(&Gdst[dst], acc[m2][n2], MD * KS, wmma::mem_row_major);
        }
}

// ---------------- hx GEMM: cp.async double-buffered, 32x32 warp tiles ----------------
struct HBuf {
    __nv_bfloat16 Ahi[64][40], Alo[64][40];    // [h][i]
    __nv_bfloat16 Bhi[128][40], Blo[128][40];  // [t][i]
};
#define HX_SMEM ((int)(2 * sizeof(HBuf)))

__device__ __forceinline__ void hx_load(HBuf& bb, int b, int h0, int t0, int i0, int tid) {
    {
        int m = tid >> 2, c = (tid & 3) * 8;
        size_t src = (size_t)(h0 + m) * MSZ + MD * ORDER + i0 + c;
        cp16(&bb.Ahi[m][c], &g_Whi[src]);
        cp16(&bb.Alo[m][c], &g_Wlo[src]);
    }
    #pragma unroll
    for (int r = 0; r < 2; ++r) {
        int e = tid + r * 256;
        int tt = e >> 2, c = (e & 3) * 8;
        size_t src = (size_t)(b * SEQ + t0 + tt) * INPUT + i0 + c;
        cp16(&bb.Bhi[tt][c], &g_xhi[src]);
        cp16(&bb.Blo[tt][c], &g_xlo[src]);
    }
}

__global__ __launch_bounds__(256, 2)
void hx_bf16_kernel(const float* __restrict__ Wh_b) {
    extern __shared__ char smem_raw[];
    HBuf* bufs = (HBuf*)smem_raw;
    __shared__ float sBias[64][16];
    int b  = blockIdx.z;
    int h0 = blockIdx.y * 64;
    int t0 = blockIdx.x * 128;
    int tid = threadIdx.x;
    int w  = tid >> 5;
    int wm = w & 1;
    int wn = w >> 1;

    #pragma unroll
    for (int r = 0; r < 4; ++r) {
        int e = tid + r * 256;
        sBias[e >> 4][e & 15] = Wh_b[h0 + (e >> 4)];
    }

    hx_load(bufs[0], b, h0, t0, 0, tid);
    cp_commit();
    __syncthreads();   // sBias ready

    FC acc[2][2];
    #pragma unroll
    for (int m2 = 0; m2 < 2; ++m2)
        #pragma unroll
        for (int n2 = 0; n2 < 2; ++n2)
            wmma::load_matrix_sync(acc[m2][n2], &sBias[wm * 32 + m2 * 16][0], 16,
                                   wmma::mem_row_major);

    #pragma unroll
    for (int it = 0; it < INPUT / 32; ++it) {
        int cur = it & 1;
        if (it + 1 < INPUT / 32) {
            hx_load(bufs[cur ^ 1], b, h0, t0, (it + 1) * 32, tid);
            cp_commit();
            asm volatile("cp.async.wait_group 1;");
        } else {
            asm volatile("cp.async.wait_group 0;");
        }
        __syncthreads();
        HBuf& bb = bufs[cur];
        #pragma unroll
        for (int kk = 0; kk < 32; kk += 16) {
            FA ahi[2], alo[2];
            #pragma unroll
            for (int m2 = 0; m2 < 2; ++m2) {
                wmma::load_matrix_sync(ahi[m2], &bb.Ahi[wm * 32 + m2 * 16][kk], 40);
                wmma::load_matrix_sync(alo[m2], &bb.Alo[wm * 32 + m2 * 16][kk], 40);
            }
            #pragma unroll
            for (int n2 = 0; n2 < 2; ++n2) {
                FBc bhi, blo;
                wmma::load_matrix_sync(bhi, &bb.Bhi[wn * 32 + n2 * 16][kk], 40);
                wmma::load_matrix_sync(blo, &bb.Blo[wn * 32 + n2 * 16][kk], 40);
                #pragma unroll
                for (int m2 = 0; m2 < 2; ++m2) {
                    wmma::mma_sync(acc[m2][n2], ahi[m2], bhi, acc[m2][n2]);
                    wmma::mma_sync(acc[m2][n2], alo[m2], bhi, acc[m2][n2]);
                    wmma::mma_sync(acc[m2][n2], ahi[m2], blo, acc[m2][n2]);
                }
            }
        }
        __syncthreads();
    }
    #pragma unroll
    for (int m2 = 0; m2 < 2; ++m2)
        #pragma unroll
        for (int n2 = 0; n2 < 2; ++n2) {
            size_t dst = ((size_t)b * HID + h0 + wm * 32 + m2 * 16) * SEQ
                       + t0 + wn * 32 + n2 * 16;
            wmma::store_matrix_sync(&g_hx[dst], acc[m2][n2], SEQ, wmma::mem_row_major);
        }
}

// ---------------- P = sum_d G*U ; real-iFFT (3x radix-16 reg passes, 2 batches) ------
__global__ __launch_bounds__(FFT_T, 2)
void pifft_kernel() {
    __shared__ float sre[2][SMSZ];
    __shared__ float sim[2][SMSZ];
    __shared__ float s_nyq[2];
    int h  = blockIdx.x >> 2;
    int bp = blockIdx.x & 3;
    int b0 = bp * 2;
    int tid = threadIdx.x;

    const float* Ur0 = g_Ure + (size_t)b0 * MD * KS;
    const float* Ui0 = g_Uim + (size_t)b0 * MD * KS;
    const float* Ur1 = Ur0 + MD * KS;
    const float* Ui1 = Ui0 + MD * KS;
    const float* Gr  = g_Gre + (size_t)h * MD * KS;
    const float* Gi  = g_Gim + (size_t)h * MD * KS;

    #pragma unroll
    for (int r = 0; r < NH / (FFT_T * 2); ++r) {
        int j = tid * 2 + r * (FFT_T * 2);
        float pr0a = 0.f, pi0a = 0.f, pr1a = 0.f, pi1a = 0.f;
        float pr0b = 0.f, pi0b = 0.f, pr1b = 0.f, pi1b = 0.f;
        #pragma unroll
        for (int d = 0; d < MD; ++d) {
            float2 gr = *(const float2*)&Gr [d * KS + j];
            float2 gi = *(const float2*)&Gi [d * KS + j];
            float2 ar = *(const float2*)&Ur0[d * KS + j];
            float2 ai = *(const float2*)&Ui0[d * KS + j];
            float2 br = *(const float2*)&Ur1[d * KS + j];
            float2 bi = *(const float2*)&Ui1[d * KS + j];
            pr0a += ar.x * gr.x - ai.x * gi.x;
            pi0a += ar.x * gi.x + ai.x * gr.x;
            pr1a += br.x * gr.x - bi.x * gi.x;
            pi1a += br.x * gi.x + bi.x * gr.x;
            pr0b += ar.y * gr.y - ai.y * gi.y;
            pi0b += ar.y * gi.y + ai.y * gr.y;
            pr1b += br.y * gr.y - bi.y * gi.y;
            pi1b += br.y * gi.y + bi.y * gr.y;
        }
        int pj = PH(j);
        sre[0][pj] = pr0a; sim[0][pj] = pi0a;
        sre[1][pj] = pr1a; sim[1][pj] = pi1a;
        int pj1 = PH(j + 1);
        sre[0][pj1] = pr0b; sim[0][pj1] = pi0b;
        sre[1][pj1] = pr1b; sim[1][pj1] = pi1b;
    }
    if (tid < 2) {
        const float* Urb = tid ? Ur1 : Ur0;
        const float* Uib = tid ? Ui1 : Ui0;
        float pn = 0.f;
        #pragma unroll
        for (int d = 0; d < MD; ++d)
            pn += Urb[d * KS + NH] * Gr[d * KS + NH] - Uib[d * KS + NH] * Gi[d * KS + NH];
        s_nyq[tid] = pn;
    }
    __syncthreads();

    float zr[2][NH / FFT_T], zi[2][NH / FFT_T];
    #pragma unroll
    for (int r = 0; r < NH / FFT_T; ++r) {
        int j = tid + r * FFT_T;
        if (j == 0) {
            #pragma unroll
            for (int q = 0; q < 2; ++q) {
                float p0 = sre[q][PH(0)], pn = s_nyq[q];
                zr[q][r] = 0.5f * (p0 + pn);
                zi[q][r] = 0.5f * (p0 - pn);
            }
        } else {
            int k = rev12(j);
            int p = rev12(NH - k);
            int pj = PH(j), pp = PH(p);
            float2 w = g_tw[k];
            #pragma unroll
            for (int q = 0; q < 2; ++q) {
                float pjr = sre[q][pj], pji = sim[q][pj];
                float ppr = sre[q][pp], ppi = sim[q][pp];
                float Xer = 0.5f * (pjr + ppr), Xei = 0.5f * (pji - ppi);
                float Dr  = 0.5f * (pjr - ppr), Di  = 0.5f * (pji + ppi);
                float Xor = w.x * Dr + w.y * Di;
                float Xoi = w.x * Di - w.y * Dr;
                zr[q][r] = Xer - Xoi;
                zi[q][r] = Xei + Xor;
            }
        }
    }
    __syncthreads();
    #pragma unroll
    for (int r = 0; r < NH / FFT_T; ++r) {
        int pj = PH(tid + r * FFT_T);
        sre[0][pj] = zr[0][r]; sim[0][pj] = zi[0][r];
        sre[1][pj] = zr[1][r]; sim[1][pj] = zi[1][r];
    }
    __syncthreads();

    {
        int q = tid >> 8;
        int g = tid & 255;
        float* qre = sre[q];
        float* qim = sim[q];
        float vr_[16], vi_[16];
        {
            int pb = PH(g << 4);
            #pragma unroll
            for (int t = 0; t < 16; ++t) { vr_[t] = qre[pb + t]; vi_[t] = qim[pb + t]; }
            fft16_dit<12>(vr_, vi_, 0, 1);
            #pragma unroll
            for (int t = 0; t < 16; ++t) { qre[pb + t] = vr_[t]; qim[pb + t] = vi_[t]; }
        }
        __syncthreads();
        {
            int base = ((g >> 4) << 8) + (g & 15);
            #pragma unroll
            for (int t = 0; t < 16; ++t) {
                int p = PH(base + (t << 4));
                vr_[t] = qre[p]; vi_[t] = qim[p];
            }
            fft16_dit<8>(vr_, vi_, g & 15, 16);
            #pragma unroll
            for (int t = 0; t < 16; ++t) {
                int p = PH(base + (t << 4));
                qre[p] = vr_[t]; qim[p] = vi_[t];
            }
        }
        __syncthreads();
        {
            #pragma unroll
            for (int t = 0; t < 16; ++t) {
                int p = PH(g + (t << 8));
                vr_[t] = qre[p]; vi_[t] = qim[p];
            }
            fft16_dit<4>(vr_, vi_, g, 256);
            #pragma unroll
            for (int t = 0; t < 16; ++t) {
                int p = PH(g + (t << 8));
                qre[p] = vr_[t]; qim[p] = vi_[t];
            }
        }
    }
    __syncthreads();

    const float inv_n = 1.0f / 4096.0f;
    #pragma unroll
    for (int q = 0; q < 2; ++q) {
        float2* hx2 = (float2*)(g_hx + (size_t)((b0 + q) * HID + h) * SEQ);
        #pragma unroll
        for (int r = 0; r < (SEQ / 2) / FFT_T; ++r) {
            int n = tid + r * FFT_T;
            int pn = PH(n);
            float2 old = hx2[n];
            float2 v;
            v.x = fmaxf(fmaf(sre[q][pn], inv_n, old.x), 0.f);
            v.y = fmaxf(fmaf(sim[q][pn], inv_n, old.y), 0.f);
            hx2[n] = v;
        }
    }
}

// ---------------- transpose [b][h][t] -> out [b][t][h] (float4 loads) ----------------
__global__ void fuse_kernel(float* __restrict__ out) {
    __shared__ float tile[32][133];
    int b  = blockIdx.z;
    int h0 = blockIdx.y * 32;
    int t0 = blockIdx.x * 128;
    int tid = threadIdx.y * 32 + threadIdx.x;

    #pragma unroll
    for (int r = 0; r < 4; ++r) {
        int e  = tid + r * 256;
        int hh = e >> 5;
        int qt = (e & 31) * 4;
        float4 v = *(const float4*)&g_hx[(size_t)(b * HID + h0 + hh) * SEQ + t0 + qt];
        tile[hh][qt + 0] = v.x;
        tile[hh][qt + 1] = v.y;
        tile[hh][qt + 2] = v.z;
        tile[hh][qt + 3] = v.w;
    }
    __syncthreads();

    int lane = tid & 31;
    int wrp  = tid >> 5;
    #pragma unroll
    for (int r = 0; r < 16; ++r) {
        int tloc = wrp + r * 8;
        out[(size_t)(b * SEQ + t0 + tloc) * HID + h0 + lane] = tile[lane][tloc];
    }
}

// ---------------- h[:, -1, :] appended after h ----------------------------------------
__global__ void last_kernel(float* __restrict__ out) {
    int i = blockIdx.x * blockDim.x + threadIdx.x;
    if (i < BATCH * HID)
        out[(size_t)BATCH * SEQ * HID + i] = g_hx[(size_t)i * SEQ + (SEQ - 1)];
}

// ---------------- launch ---------------------------------------------------------------
extern "C" void kernel_launch(void* const* d_in, const int* in_sizes, int n_in,
                              void* d_out, int out_size) {
    const float* x    = (const float*)d_in[0];
    const float* Wu_w = (const float*)d_in[1];
    const float* Wu_b = (const float*)d_in[2];
    const float* Wh_w = (const float*)d_in[3];
    const float* Wh_b = (const float*)d_in[4];
    const float* H    = (const float*)d_in[5];
    float* out = (float*)d_out;

    static int configured = 0;
    if (!configured) {
        cudaFuncSetAttribute(gbuild_bf16_kernel,
                             cudaFuncAttributeMaxDynamicSharedMemorySize, GB_SMEM);
        cudaFuncSetAttribute(hx_bf16_kernel,
                             cudaFuncAttributeMaxDynamicSharedMemorySize, HX_SMEM);
        configured = 1;
    }

    setup_kernel<<<(HID * MSZ + 511) / 512, 512>>>(Wh_w);
    u_kernel<<<(BATCH * SEQ * 32) / 256, 256>>>(x, Wu_w, Wu_b);

    fft_fwd_kernel<<<32 + ORDER, FFT_T>>>(H);      // u + H spectra, one launch

    gbuild_bf16_kernel<<<dim3(KS / 128, HID / 64, MD * 2), 256, GB_SMEM>>>();
    hx_bf16_kernel<<<dim3(SEQ / 128, HID / 64, BATCH), 256, HX_SMEM>>>(Wh_b);

    pifft_kernel<<<HID * BATCH / 2, FFT_T>>>();

    fuse_kernel<<<dim3(SEQ / 128, HID / 32, BATCH), dim3(32, 8)>>>(out);
    if (out_size >= BATCH * SEQ * HID + BATCH * HID)
        last_kernel<<<8, 512>>>(out);
}

// round 16
// speedup vs baseline: 1.0792x; 1.0792x over previous
#include <cuda_runtime.h>
#include <cuda_bf16.h>
#include <mma.h>
#include <math.h>

using namespace nvcuda;

#define SEQ   4096
#define BATCH 8
#define MD    4
#define ORDER 256
#define INPUT 256
#define HID   512
#define MSZ   1280
#define NH    4096      // complex FFT size (= 8192/2), real-FFT packing
#define LOGH  12
#define KS    4224      // spectrum row stride (33*128)
#define FFT_T 512

// padded smem index map: +1 word every 16 -> conflict-free radix-16 passes.
#define PH(i) ((i) + ((i) >> 4))
#define SMSZ  4352

typedef wmma::fragment<wmma::matrix_a, 16, 16, 16, __nv_bfloat16, wmma::row_major> FA;
typedef wmma::fragment<wmma::matrix_b, 16, 16, 16, __nv_bfloat16, wmma::row_major> FBr;
typedef wmma::fragment<wmma::matrix_b, 16, 16, 16, __nv_bfloat16, wmma::col_major> FBc;
typedef wmma::fragment<wmma::accumulator, 16, 16, 16, float> FC;

// ---------------- scratch (static device globals; no allocation) -----------------
__device__ float  g_u  [32 * SEQ];
__device__ float2 g_tw [NH];            // e^{-2*pi*i*k/8192}
__device__ float  g_Ure[32 * KS];
__device__ float  g_Uim[32 * KS];
__device__ __nv_bfloat16 g_Hrehi[ORDER * KS];
__device__ __nv_bfloat16 g_Hrelo[ORDER * KS];
__device__ __nv_bfloat16 g_Himhi[ORDER * KS];
__device__ __nv_bfloat16 g_Himlo[ORDER * KS];
__device__ __nv_bfloat16 g_Whi[HID * MSZ];
__device__ __nv_bfloat16 g_Wlo[HID * MSZ];
__device__ __nv_bfloat16 g_xhi[BATCH * SEQ * INPUT];
__device__ __nv_bfloat16 g_xlo[BATCH * SEQ * INPUT];
__device__ float  g_Gre[HID * MD * KS];
__device__ float  g_Gim[HID * MD * KS];
__device__ float  g_hx [BATCH * HID * SEQ];  // h (pre-relu then relu'd), [b][h][t]

__device__ __forceinline__ int rev12(int x) { return (int)(__brev((unsigned)x) >> 20); }

__device__ __forceinline__ void bsplit(float v, __nv_bfloat16& hi, __nv_bfloat16& lo) {
    hi = __float2bfloat16(v);
    lo = __float2bfloat16(v - __bfloat162float(hi));
}

// 16-byte async copy global -> shared (LDGSTS)
__device__ __forceinline__ void cp16(void* smem, const void* gmem) {
    unsigned sa = (unsigned)__cvta_generic_to_shared(smem);
    asm volatile("cp.async.cg.shared.global [%0], [%1], 16;" :: "r"(sa), "l"(gmem));
}
__device__ __forceinline__ void cp_commit() { asm volatile("cp.async.commit_group;"); }

// 4 radix-2 DIT stages (conj twiddles) on 16 register-resident points.
// Twiddles via per-stage complex recurrence: 1 gather (wb) + 1 broadcast (ws)
// per stage instead of per-butterfly gathers.
template<int SHIFT>
__device__ __forceinline__ void fft16_dit(float* vr_, float* vi_, int jbase, int stride) {
    #pragma unroll
    for (int ss = 0; ss < 4; ++ss) {
        int mloc = 1 << ss;
        float2 w = g_tw[jbase << (SHIFT - ss)];
        float2 ws = make_float2(1.f, 0.f);
        if (ss > 0) ws = g_tw[stride << (SHIFT - ss)];   // lane-invariant
        #pragma unroll
        for (int q = 0; q < 8; ++q) {
            if (q < mloc) {
                #pragma unroll
                for (int gi = 0; gi < 8; ++gi) {
                    if (gi < (8 >> ss)) {
                        int t0 = (gi << (ss + 1)) | q;
                        int t1 = t0 + mloc;
                        float br = vr_[t1], bi = vi_[t1];
                        float pr = br * w.x + bi * w.y;      // conj twiddle
                        float pi = bi * w.x - br * w.y;
                        float ar = vr_[t0], ai = vi_[t0];
                        vr_[t0] = ar + pr;  vi_[t0] = ai + pi;
                        vr_[t1] = ar - pr;  vi_[t1] = ai - pi;
                    }
                }
                float2 wn;                                   // w <- w * ws
                wn.x = w.x * ws.x - w.y * ws.y;
                wn.y = w.x * ws.y + w.y * ws.x;
                w = wn;
            }
        }
    }
}

// ---------------- setup: twiddle table + Wh hi/lo split (one launch) -----------------
__global__ void setup_kernel(const float* __restrict__ Wh_w) {
    int i = blockIdx.x * blockDim.x + threadIdx.x;
    if (i < NH) {
        float s, c;
        sincospif(-(float)i / 4096.0f, &s, &c);
        g_tw[i] = make_float2(c, s);
    }
    if (i < HID * MSZ) bsplit(Wh_w[i], g_Whi[i], g_Wlo[i]);
}

// ---------------- u = relu(x @ Wu^T + b), fused x hi/lo split -------------------------
__global__ void u_kernel(const float* __restrict__ x,
                         const float* __restrict__ Wu_w,
                         const float* __restrict__ Wu_b) {
    int gw   = (blockIdx.x * blockDim.x + threadIdx.x) >> 5;
    int lane = threadIdx.x & 31;
    if (gw >= BATCH * SEQ) return;
    int b = gw >> 12, t = gw & (SEQ - 1);
    size_t rowoff = (size_t)(b * SEQ + t) * INPUT;
    const float* xp = x + rowoff;
    float a0 = 0.f, a1 = 0.f, a2 = 0.f, a3 = 0.f;
    #pragma unroll
    for (int i = lane; i < INPUT; i += 32) {
        float xv = xp[i];
        __nv_bfloat16 hi, lo;
        bsplit(xv, hi, lo);
        g_xhi[rowoff + i] = hi;
        g_xlo[rowoff + i] = lo;
        a0 = fmaf(xv, __ldg(&Wu_w[0 * INPUT + i]), a0);
        a1 = fmaf(xv, __ldg(&Wu_w[1 * INPUT + i]), a1);
        a2 = fmaf(xv, __ldg(&Wu_w[2 * INPUT + i]), a2);
        a3 = fmaf(xv, __ldg(&Wu_w[3 * INPUT + i]), a3);
    }
    #pragma unroll
    for (int off = 16; off; off >>= 1) {
        a0 += __shfl_down_sync(0xffffffffu, a0, off);
        a1 += __shfl_down_sync(0xffffffffu, a1, off);
        a2 += __shfl_down_sync(0xffffffffu, a2, off);
        a3 += __shfl_down_sync(0xffffffffu, a3, off);
    }
    if (lane == 0) {
        g_u[(b * 4 + 0) * SEQ + t] = fmaxf(a0 + Wu_b[0], 0.f);
        g_u[(b * 4 + 1) * SEQ + t] = fmaxf(a1 + Wu_b[1], 0.f);
        g_u[(b * 4 + 2) * SEQ + t] = fmaxf(a2 + Wu_b[2], 0.f);
        g_u[(b * 4 + 3) * SEQ + t] = fmaxf(a3 + Wu_b[3], 0.f);
    }
}

// ---------------- forward real FFT, both inputs in ONE launch -------------------------
__global__ void fft_fwd_kernel(const float* __restrict__ Hin) {
    __shared__ float sre[NH];
    __shared__ float sim[NH];
    int blk = blockIdx.x;
    int mode = (blk >= 32);
    int row = mode ? (blk - 32) : blk;
    int tid = threadIdx.x;
    const float* in = mode ? (Hin + (size_t)row * SEQ) : (g_u + (size_t)row * SEQ);

    const float2* in2 = (const float2*)in;
    #pragma unroll
    for (int r = 0; r < NH / FFT_T; ++r) {
        int n = tid + r * FFT_T;
        if (n < SEQ / 2) { float2 v = in2[n]; sre[n] = v.x; sim[n] = v.y; }
        else             { sre[n] = 0.f;      sim[n] = 0.f; }
    }
    __syncthreads();

    #pragma unroll
    for (int s = LOGH - 2; s >= 0; s -= 2) {
        int m = 1 << s;
        #pragma unroll
        for (int r = 0; r < (NH / 4) / FFT_T; ++r) {
            int k = tid + r * FFT_T;
            int j = k & (m - 1);
            int base = ((k >> s) << (s + 2)) + j;
            int ia = base, ib = base + m, ic = base + 2 * m, id = base + 3 * m;
            float2 w2 = g_tw[j << (LOGH - s - 1)];
            float2 w1 = g_tw[j << (LOGH - s)];
            float ar = sre[ia], ai = sim[ia];
            float br = sre[ib], bi = sim[ib];
            float cr = sre[ic], ci = sim[ic];
            float dr = sre[id], di = sim[id];
            float a1r = ar + cr, a1i = ai + ci;
            float tr  = ar - cr, ti  = ai - ci;
            float c1r = tr * w2.x - ti * w2.y;
            float c1i = tr * w2.y + ti * w2.x;
            float b1r = br + dr, b1i = bi + di;
            tr = br - dr; ti = bi - di;
            float er = tr * w2.x - ti * w2.y;
            float ei = tr * w2.y + ti * w2.x;
            float d1r = ei, d1i = -er;                     // * (-i)
            sre[ia] = a1r + b1r;  sim[ia] = a1i + b1i;
            tr = a1r - b1r; ti = a1i - b1i;
            sre[ib] = tr * w1.x - ti * w1.y;
            sim[ib] = tr * w1.y + ti * w1.x;
            sre[ic] = c1r + d1r;  sim[ic] = c1i + d1i;
            tr = c1r - d1r; ti = c1i - d1i;
            sre[id] = tr * w1.x - ti * w1.y;
            sim[id] = tr * w1.y + ti * w1.x;
        }
        __syncthreads();
    }

    if (mode == 0) {
        float* outre = g_Ure + (size_t)row * KS;
        float* outim = g_Uim + (size_t)row * KS;
        #pragma unroll
        for (int r = 0; r < NH / FFT_T; ++r) {
            int j = tid + r * FFT_T;
            if (j == 0) {
                float zr = sre[0], zi = sim[0];
                outre[0]  = zr + zi;  outim[0]  = 0.f;
                outre[NH] = zr - zi;  outim[NH] = 0.f;
            } else {
                int k = rev12(j);
                int p = rev12(NH - k);
                float zjr = sre[j], zji = sim[j];
                float zpr = sre[p], zpi = sim[p];
                float Ar = 0.5f * (zjr + zpr), Ai = 0.5f * (zji - zpi);
                float Br = 0.5f * (zji + zpi), Bi = -0.5f * (zjr - zpr);
                float2 w = g_tw[k];
                outre[j] = Ar + w.x * Br - w.y * Bi;
                outim[j] = Ai + w.x * Bi + w.y * Br;
            }
        }
    } else {
        size_t off = (size_t)row * KS;
        for (int pcol = NH + 1 + tid; pcol < KS; pcol += FFT_T) {
            g_Hrehi[off + pcol] = __float2bfloat16(0.f);
            g_Hrelo[off + pcol] = __float2bfloat16(0.f);
            g_Himhi[off + pcol] = __float2bfloat16(0.f);
            g_Himlo[off + pcol] = __float2bfloat16(0.f);
        }
        #pragma unroll
        for (int r = 0; r < NH / FFT_T; ++r) {
            int j = tid + r * FFT_T;
            float vre, vim;
            if (j == 0) {
                float zr = sre[0], zi = sim[0];
                vre = zr + zi; vim = 0.f;
                float nre = zr - zi;
                bsplit(nre, g_Hrehi[off + NH], g_Hrelo[off + NH]);
                bsplit(0.f, g_Himhi[off + NH], g_Himlo[off + NH]);
            } else {
                int k = rev12(j);
                int p = rev12(NH - k);
                float zjr = sre[j], zji = sim[j];
                float zpr = sre[p], zpi = sim[p];
                float Ar = 0.5f * (zjr + zpr), Ai = 0.5f * (zji - zpi);
                float Br = 0.5f * (zji + zpi), Bi = -0.5f * (zjr - zpr);
                float2 w = g_tw[k];
                vre = Ar + w.x * Br - w.y * Bi;
                vim = Ai + w.x * Bi + w.y * Br;
            }
            bsplit(vre, g_Hrehi[off + j], g_Hrelo[off + j]);
            bsplit(vim, g_Himhi[off + j], g_Himlo[off + j]);
        }
    }
}

// ---------------- G build: cp.async double-buffered bf16-split GEMM (R14 best) -------
struct GBuf {
    __nv_bfloat16 Ahi[64][40], Alo[64][40];          // [m][k]
    __nv_bfloat16 Bhi[2][32][136], Blo[2][32][136];  // [re/im][k][n]
};
#define GB_SMEM ((int)(2 * sizeof(GBuf)))

__device__ __forceinline__ void gbuild_load(GBuf& bb, int d, int h0, int k0, int o0, int tid) {
    {
        int m = tid >> 2, c = (tid & 3) * 8;
        size_t src = (size_t)(h0 + m) * MSZ + d * ORDER + o0 + c;
        cp16(&bb.Ahi[m][c], &g_Whi[src]);
        cp16(&bb.Alo[m][c], &g_Wlo[src]);
    }
    #pragma unroll
    for (int r = 0; r < 2; ++r) {
        int oo = (tid >> 4) + r * 16;
        int c  = (tid & 15) * 8;
        size_t src = (size_t)(o0 + oo) * KS + k0 + c;
        cp16(&bb.Bhi[0][oo][c], &g_Hrehi[src]);
        cp16(&bb.Blo[0][oo][c], &g_Hrelo[src]);
        cp16(&bb.Bhi[1][oo][c], &g_Himhi[src]);
        cp16(&bb.Blo[1][oo][c], &g_Himlo[src]);
    }
}

__global__ __launch_bounds__(256)
void gbuild_bf16_kernel() {
    extern __shared__ char smem_raw[];
    GBuf* bufs = (GBuf*)smem_raw;
    int d  = blockIdx.z;
    int h0 = blockIdx.y * 64;
    int k0 = blockIdx.x * 128;
    int tid = threadIdx.x;
    int w  = tid >> 5;
    int wm = w & 1;
    int wn = w >> 1;

    FC accr[2][2], acci[2][2];
    #pragma unroll
    for (int m2 = 0; m2 < 2; ++m2)
        #pragma unroll
        for (int n2 = 0; n2 < 2; ++n2) {
            wmma::fill_fragment(accr[m2][n2], 0.f);
            wmma::fill_fragment(acci[m2][n2], 0.f);
        }

    gbuild_load(bufs[0], d, h0, k0, 0, tid);
    cp_commit();

    #pragma unroll
    for (int it = 0; it < ORDER / 32; ++it) {
        int cur = it & 1;
        if (it + 1 < ORDER / 32) {
            gbuild_load(bufs[cur ^ 1], d, h0, k0, (it + 1) * 32, tid);
            cp_commit();
            asm volatile("cp.async.wait_group 1;");
        } else {
            asm volatile("cp.async.wait_group 0;");
        }
        __syncthreads();
        GBuf& bb = bufs[cur];
        #pragma unroll
        for (int kk = 0; kk < 32; kk += 16) {
            FA ahi[2], alo[2];
            #pragma unroll
            for (int m2 = 0; m2 < 2; ++m2) {
                wmma::load_matrix_sync(ahi[m2], &bb.Ahi[wm * 32 + m2 * 16][kk], 40);
                wmma::load_matrix_sync(alo[m2], &bb.Alo[wm * 32 + m2 * 16][kk], 40);
            }
            #pragma unroll
            for (int n2 = 0; n2 < 2; ++n2) {
                FBr bhi, blo;
                wmma::load_matrix_sync(bhi, &bb.Bhi[0][kk][wn * 32 + n2 * 16], 136);
                wmma::load_matrix_sync(blo, &bb.Blo[0][kk][wn * 32 + n2 * 16], 136);
                #pragma unroll
                for (int m2 = 0; m2 < 2; ++m2) {
                    wmma::mma_sync(accr[m2][n2], ahi[m2], bhi, accr[m2][n2]);
                    wmma::mma_sync(accr[m2][n2], alo[m2], bhi, accr[m2][n2]);
                    wmma::mma_sync(accr[m2][n2], ahi[m2], blo, accr[m2][n2]);
                }
                wmma::load_matrix_sync(bhi, &bb.Bhi[1][kk][wn * 32 + n2 * 16], 136);
                wmma::load_matrix_sync(blo, &bb.Blo[1][kk][wn * 32 + n2 * 16], 136);
                #pragma unroll
                for (int m2 = 0; m2 < 2; ++m2) {
                    wmma::mma_sync(acci[m2][n2], ahi[m2], bhi, acci[m2][n2]);
                    wmma::mma_sync(acci[m2][n2], alo[m2], bhi, acci[m2][n2]);
                    wmma::mma_sync(acci[m2][n2], ahi[m2], blo, acci[m2][n2]);
                }
            }
        }
        __syncthreads();
    }
    #pragma unroll
    for (int m2 = 0; m2 < 2; ++m2)
        #pragma unroll
        for (int n2 = 0; n2 < 2; ++n2) {
            size_t dst = ((size_t)(h0 + wm * 32 + m2 * 16) * MD + d) * KS
                       + k0 + wn * 32 + n2 * 16;
            wmma::store_matrix_sync(&g_Gre[dst], accr[m2][n2], MD * KS, wmma::mem_row_major);
            wmma::store_matrix_sync(&g_Gim[dst], acci[m2][n2], MD * KS, wmma::mem_row_major);
        }
}

// ---------------- hx GEMM: cp.async double-buffered, 32x32 warp tiles ----------------
struct HBuf {
    __nv_bfloat16 Ahi[64][40], Alo[64][40];    // [h][i]
    __nv_bfloat16 Bhi[128][40], Blo[128][40];  // [t][i]
};
#define HX_SMEM ((int)(2 * sizeof(HBuf)))

__device__ __forceinline__ void hx_load(HBuf& bb, int b, int h0, int t0, int i0, int tid) {
    {
        int m = tid >> 2, c = (tid & 3) * 8;
        size_t src = (size_t)(h0 + m) * MSZ + MD * ORDER + i0 + c;
        cp16(&bb.Ahi[m][c], &g_Whi[src]);
        cp16(&bb.Alo[m][c], &g_Wlo[src]);
    }
    #pragma unroll
    for (int r = 0; r < 2; ++r) {
        int e = tid + r * 256;
        int tt = e >> 2, c = (e & 3) * 8;
        size_t src = (size_t)(b * SEQ + t0 + tt) * INPUT + i0 + c;
        cp16(&bb.Bhi[tt][c], &g_xhi[src]);
        cp16(&bb.Blo[tt][c], &g_xlo[src]);
    }
}

__global__ __launch_bounds__(256)
void hx_bf16_kernel(const float* __restrict__ Wh_b) {
    extern __shared__ char smem_raw[];
    HBuf* bufs = (HBuf*)smem_raw;
    __shared__ float sBias[64][16];
    int b  = blockIdx.z;
    int h0 = blockIdx.y * 64;
    int t0 = blockIdx.x * 128;
    int tid = threadIdx.x;
    int w  = tid >> 5;
    int wm = w & 1;
    int wn = w >> 1;

    #pragma unroll
    for (int r = 0; r < 4; ++r) {
        int e = tid + r * 256;
        sBias[e >> 4][e & 15] = Wh_b[h0 + (e >> 4)];
    }

    hx_load(bufs[0], b, h0, t0, 0, tid);
    cp_commit();
    __syncthreads();   // sBias ready

    FC acc[2][2];
    #pragma unroll
    for (int m2 = 0; m2 < 2; ++m2)
        #pragma unroll
        for (int n2 = 0; n2 < 2; ++n2)
            wmma::load_matrix_sync(acc[m2][n2], &sBias[wm * 32 + m2 * 16][0], 16,
                                   wmma::mem_row_major);

    #pragma unroll
    for (int it = 0; it < INPUT / 32; ++it) {
        int cur = it & 1;
        if (it + 1 < INPUT / 32) {
            hx_load(bufs[cur ^ 1], b, h0, t0, (it + 1) * 32, tid);
            cp_commit();
            asm volatile("cp.async.wait_group 1;");
        } else {
            asm volatile("cp.async.wait_group 0;");
        }
        __syncthreads();
        HBuf& bb = bufs[cur];
        #pragma unroll
        for (int kk = 0; kk < 32; kk += 16) {
            FA ahi[2], alo[2];
            #pragma unroll
            for (int m2 = 0; m2 < 2; ++m2) {
                wmma::load_matrix_sync(ahi[m2], &bb.Ahi[wm * 32 + m2 * 16][kk], 40);
                wmma::load_matrix_sync(alo[m2], &bb.Alo[wm * 32 + m2 * 16][kk], 40);
            }
            #pragma unroll
            for (int n2 = 0; n2 < 2; ++n2) {
                FBc bhi, blo;
                wmma::load_matrix_sync(bhi, &bb.Bhi[wn * 32 + n2 * 16][kk], 40);
                wmma::load_matrix_sync(blo, &bb.Blo[wn * 32 + n2 * 16][kk], 40);
                #pragma unroll
                for (int m2 = 0; m2 < 2; ++m2) {
                    wmma::mma_sync(acc[m2][n2], ahi[m2], bhi, acc[m2][n2]);
                    wmma::mma_sync(acc[m2][n2], alo[m2], bhi, acc[m2][n2]);
                    wmma::mma_sync(acc[m2][n2], ahi[m2], blo, acc[m2][n2]);
                }
            }
        }
        __syncthreads();
    }
    #pragma unroll
    for (int m2 = 0; m2 < 2; ++m2)
        #pragma unroll
        for (int n2 = 0; n2 < 2; ++n2) {
            size_t dst = ((size_t)b * HID + h0 + wm * 32 + m2 * 16) * SEQ
                       + t0 + wn * 32 + n2 * 16;
            wmma::store_matrix_sync(&g_hx[dst], acc[m2][n2], SEQ, wmma::mem_row_major);
        }
}

// ---------------- P = sum_d G*U ; real-iFFT (3x radix-16 reg passes, 2 batches) ------
__global__ __launch_bounds__(FFT_T, 2)
void pifft_kernel() {
    __shared__ float sre[2][SMSZ];
    __shared__ float sim[2][SMSZ];
    __shared__ float s_nyq[2];
    int h  = blockIdx.x >> 2;
    int bp = blockIdx.x & 3;
    int b0 = bp * 2;
    int tid = threadIdx.x;

    const float* Ur0 = g_Ure + (size_t)b0 * MD * KS;
    const float* Ui0 = g_Uim + (size_t)b0 * MD * KS;
    const float* Ur1 = Ur0 + MD * KS;
    const float* Ui1 = Ui0 + MD * KS;
    const float* Gr  = g_Gre + (size_t)h * MD * KS;
    const float* Gi  = g_Gim + (size_t)h * MD * KS;

    #pragma unroll
    for (int r = 0; r < NH / (FFT_T * 2); ++r) {
        int j = tid * 2 + r * (FFT_T * 2);
        float pr0a = 0.f, pi0a = 0.f, pr1a = 0.f, pi1a = 0.f;
        float pr0b = 0.f, pi0b = 0.f, pr1b = 0.f, pi1b = 0.f;
        #pragma unroll
        for (int d = 0; d < MD; ++d) {
            float2 gr = *(const float2*)&Gr [d * KS + j];
            float2 gi = *(const float2*)&Gi [d * KS + j];
            float2 ar = *(const float2*)&Ur0[d * KS + j];
            float2 ai = *(const float2*)&Ui0[d * KS + j];
            float2 br = *(const float2*)&Ur1[d * KS + j];
            float2 bi = *(const float2*)&Ui1[d * KS + j];
            pr0a += ar.x * gr.x - ai.x * gi.x;
            pi0a += ar.x * gi.x + ai.x * gr.x;
            pr1a += br.x * gr.x - bi.x * gi.x;
            pi1a += br.x * gi.x + bi.x * gr.x;
            pr0b += ar.y * gr.y - ai.y * gi.y;
            pi0b += ar.y * gi.y + ai.y * gr.y;
            pr1b += br.y * gr.y - bi.y * gi.y;
            pi1b += br.y * gi.y + bi.y * gr.y;
        }
        int pj = PH(j);
        sre[0][pj] = pr0a; sim[0][pj] = pi0a;
        sre[1][pj] = pr1a; sim[1][pj] = pi1a;
        int pj1 = PH(j + 1);
        sre[0][pj1] = pr0b; sim[0][pj1] = pi0b;
        sre[1][pj1] = pr1b; sim[1][pj1] = pi1b;
    }
    if (tid < 2) {
        const float* Urb = tid ? Ur1 : Ur0;
        const float* Uib = tid ? Ui1 : Ui0;
        float pn = 0.f;
        #pragma unroll
        for (int d = 0; d < MD; ++d)
            pn += Urb[d * KS + NH] * Gr[d * KS + NH] - Uib[d * KS + NH] * Gi[d * KS + NH];
        s_nyq[tid] = pn;
    }
    __syncthreads();

    float zr[2][NH / FFT_T], zi[2][NH / FFT_T];
    #pragma unroll
    for (int r = 0; r < NH / FFT_T; ++r) {
        int j = tid + r * FFT_T;
        if (j == 0) {
            #pragma unroll
            for (int q = 0; q < 2; ++q) {
                float p0 = sre[q][PH(0)], pn = s_nyq[q];
                zr[q][r] = 0.5f * (p0 + pn);
                zi[q][r] = 0.5f * (p0 - pn);
            }
        } else {
            int k = rev12(j);
            int p = rev12(NH - k);
            int pj = PH(j), pp = PH(p);
            float2 w = g_tw[k];
            #pragma unroll
            for (int q = 0; q < 2; ++q) {
                float pjr = sre[q][pj], pji = sim[q][pj];
                float ppr = sre[q][pp], ppi = sim[q][pp];
                float Xer = 0.5f * (pjr + ppr), Xei = 0.5f * (pji - ppi);
                float Dr  = 0.5f * (pjr - ppr), Di  = 0.5f * (pji + ppi);
                float Xor = w.x * Dr + w.y * Di;
                float Xoi = w.x * Di - w.y * Dr;
                zr[q][r] = Xer - Xoi;
                zi[q][r] = Xei + Xor;
            }
        }
    }
    __syncthreads();
    #pragma unroll
    for (int r = 0; r < NH / FFT_T; ++r) {
        int pj = PH(tid + r * FFT_T);
        sre[0][pj] = zr[0][r]; sim[0][pj] = zi[0][r];
        sre[1][pj] = zr[1][r]; sim[1][pj] = zi[1][r];
    }
    __syncthreads();

    {
        int q = tid >> 8;
        int g = tid & 255;
        float* qre = sre[q];
        float* qim = sim[q];
        float vr_[16], vi_[16];
        {
            int pb = PH(g << 4);
            #pragma unroll
            for (int t = 0; t < 16; ++t) { vr_[t] = qre[pb + t]; vi_[t] = qim[pb + t]; }
            fft16_dit<12>(vr_, vi_, 0, 1);
            #pragma unroll
            for (int t = 0; t < 16; ++t) { qre[pb + t] = vr_[t]; qim[pb + t] = vi_[t]; }
        }
        __syncthreads();
        {
            int base = ((g >> 4) << 8) + (g & 15);
            #pragma unroll
            for (int t = 0; t < 16; ++t) {
                int p = PH(base + (t << 4));
                vr_[t] = qre[p]; vi_[t] = qim[p];
            }
            fft16_dit<8>(vr_, vi_, g & 15, 16);
            #pragma unroll
            for (int t = 0; t < 16; ++t) {
                int p = PH(base + (t << 4));
                qre[p] = vr_[t]; qim[p] = vi_[t];
            }
        }
        __syncthreads();
        {
            #pragma unroll
            for (int t = 0; t < 16; ++t) {
                int p = PH(g + (t << 8));
                vr_[t] = qre[p]; vi_[t] = qim[p];
            }
            fft16_dit<4>(vr_, vi_, g, 256);
            #pragma unroll
            for (int t = 0; t < 16; ++t) {
                int p = PH(g + (t << 8));
                qre[p] = vr_[t]; qim[p] = vi_[t];
            }
        }
    }
    __syncthreads();

    const float inv_n = 1.0f / 4096.0f;
    #pragma unroll
    for (int q = 0; q < 2; ++q) {
        float2* hx2 = (float2*)(g_hx + (size_t)((b0 + q) * HID + h) * SEQ);
        #pragma unroll
        for (int r = 0; r < (SEQ / 2) / FFT_T; ++r) {
            int n = tid + r * FFT_T;
            int pn = PH(n);
            float2 old = hx2[n];
            float2 v;
            v.x = fmaxf(fmaf(sre[q][pn], inv_n, old.x), 0.f);
            v.y = fmaxf(fmaf(sim[q][pn], inv_n, old.y), 0.f);
            hx2[n] = v;
        }
    }
}

// ---------------- transpose [b][h][t] -> out [b][t][h] (float4 loads) ----------------
__global__ void fuse_kernel(float* __restrict__ out) {
    __shared__ float tile[32][133];
    int b  = blockIdx.z;
    int h0 = blockIdx.y * 32;
    int t0 = blockIdx.x * 128;
    int tid = threadIdx.y * 32 + threadIdx.x;

    #pragma unroll
    for (int r = 0; r < 4; ++r) {
        int e  = tid + r * 256;
        int hh = e >> 5;
        int qt = (e & 31) * 4;
        float4 v = *(const float4*)&g_hx[(size_t)(b * HID + h0 + hh) * SEQ + t0 + qt];
        tile[hh][qt + 0] = v.x;
        tile[hh][qt + 1] = v.y;
        tile[hh][qt + 2] = v.z;
        tile[hh][qt + 3] = v.w;
    }
    __syncthreads();

    int lane = tid & 31;
    int wrp  = tid >> 5;
    #pragma unroll
    for (int r = 0; r < 16; ++r) {
        int tloc = wrp + r * 8;
        out[(size_t)(b * SEQ + t0 + tloc) * HID + h0 + lane] = tile[lane][tloc];
    }
}

// ---------------- h[:, -1, :] appended after h ----------------------------------------
__global__ void last_kernel(float* __restrict__ out) {
    int i = blockIdx.x * blockDim.x + threadIdx.x;
    if (i < BATCH * HID)
        out[(size_t)BATCH * SEQ * HID + i] = g_hx[(size_t)i * SEQ + (SEQ - 1)];
}

// ---------------- launch ---------------------------------------------------------------
extern "C" void kernel_launch(void* const* d_in, const int* in_sizes, int n_in,
                              void* d_out, int out_size) {
    const float* x    = (const float*)d_in[0];
    const float* Wu_w = (const float*)d_in[1];
    const float* Wu_b = (const float*)d_in[2];
    const float* Wh_w = (const float*)d_in[3];
    const float* Wh_b = (const float*)d_in[4];
    const float* H    = (const float*)d_in[5];
    float* out = (float*)d_out;

    static int configured = 0;
    if (!configured) {
        cudaFuncSetAttribute(gbuild_bf16_kernel,
                             cudaFuncAttributeMaxDynamicSharedMemorySize, GB_SMEM);
        cudaFuncSetAttribute(hx_bf16_kernel,
                             cudaFuncAttributeMaxDynamicSharedMemorySize, HX_SMEM);
        configured = 1;
    }

    setup_kernel<<<(HID * MSZ + 511) / 512, 512>>>(Wh_w);
    u_kernel<<<(BATCH * SEQ * 32) / 256, 256>>>(x, Wu_w, Wu_b);

    fft_fwd_kernel<<<32 + ORDER, FFT_T>>>(H);      // u + H spectra, one launch

    gbuild_bf16_kernel<<<dim3(KS / 128, HID / 64, MD), 256, GB_SMEM>>>();
    hx_bf16_kernel<<<dim3(SEQ / 128, HID / 64, BATCH), 256, HX_SMEM>>>(Wh_b);

    pifft_kernel<<<HID * BATCH / 2, FFT_T>>>();

    fuse_kernel<<<dim3(SEQ / 128, HID / 32, BATCH), dim3(32, 8)>>>(out);
    if (out_size >= BATCH * SEQ * HID + BATCH * HID)
        last_kernel<<<8, 512>>>(out);
}

// round 17
// speedup vs baseline: 1.1359x; 1.0526x over previous
#include <cuda_runtime.h>
#include <cuda_bf16.h>
#include <mma.h>
#include <math.h>

using namespace nvcuda;

#define SEQ   4096
#define BATCH 8
#define MD    4
#define ORDER 256
#define INPUT 256
#define HID   512
#define MSZ   1280
#define NH    4096      // complex FFT size (= 8192/2), real-FFT packing
#define LOGH  12
#define KS    4224      // spectrum row stride (33*128)
#define FFT_T 512

// padded smem index map: +1 word every 16 -> conflict-free radix-16 passes.
#define PH(i) ((i) + ((i) >> 4))
#define SMSZ  4352

typedef wmma::fragment<wmma::matrix_a, 16, 16, 16, __nv_bfloat16, wmma::row_major> FA;
typedef wmma::fragment<wmma::matrix_b, 16, 16, 16, __nv_bfloat16, wmma::row_major> FBr;
typedef wmma::fragment<wmma::matrix_b, 16, 16, 16, __nv_bfloat16, wmma::col_major> FBc;
typedef wmma::fragment<wmma::accumulator, 16, 16, 16, float> FC;

// ---------------- scratch (static device globals; no allocation) -----------------
__device__ float  g_u  [32 * SEQ];
__device__ float2 g_tw [NH];            // e^{-2*pi*i*k/8192}
__device__ float  g_Ure[32 * KS];
__device__ float  g_Uim[32 * KS];
__device__ __nv_bfloat16 g_Hrehi[ORDER * KS];
__device__ __nv_bfloat16 g_Hrelo[ORDER * KS];
__device__ __nv_bfloat16 g_Himhi[ORDER * KS];
__device__ __nv_bfloat16 g_Himlo[ORDER * KS];
__device__ __nv_bfloat16 g_Whi[HID * MSZ];
__device__ __nv_bfloat16 g_Wlo[HID * MSZ];
__device__ __nv_bfloat16 g_xhi[BATCH * SEQ * INPUT];
__device__ __nv_bfloat16 g_xlo[BATCH * SEQ * INPUT];
__device__ float  g_Gre[HID * MD * KS];
__device__ float  g_Gim[HID * MD * KS];
__device__ float  g_hx [BATCH * HID * SEQ];  // h (pre-relu then relu'd), [b][h][t]

__device__ __forceinline__ int rev12(int x) { return (int)(__brev((unsigned)x) >> 20); }

__device__ __forceinline__ void bsplit(float v, __nv_bfloat16& hi, __nv_bfloat16& lo) {
    hi = __float2bfloat16(v);
    lo = __float2bfloat16(v - __bfloat162float(hi));
}

// 16-byte async copy global -> shared (LDGSTS)
__device__ __forceinline__ void cp16(void* smem, const void* gmem) {
    unsigned sa = (unsigned)__cvta_generic_to_shared(smem);
    asm volatile("cp.async.cg.shared.global [%0], [%1], 16;" :: "r"(sa), "l"(gmem));
}
__device__ __forceinline__ void cp_commit() { asm volatile("cp.async.commit_group;"); }

// 4 radix-2 DIT stages (conj twiddles) on 16 register-resident points.
// Twiddles via per-stage complex recurrence: 1 gather + 1 broadcast per stage.
template<int SHIFT>
__device__ __forceinline__ void fft16_dit(float* vr_, float* vi_, int jbase, int stride) {
    #pragma unroll
    for (int ss = 0; ss < 4; ++ss) {
        int mloc = 1 << ss;
        float2 w = g_tw[jbase << (SHIFT - ss)];
        float2 ws = make_float2(1.f, 0.f);
        if (ss > 0) ws = g_tw[stride << (SHIFT - ss)];   // lane-invariant
        #pragma unroll
        for (int q = 0; q < 8; ++q) {
            if (q < mloc) {
                #pragma unroll
                for (int gi = 0; gi < 8; ++gi) {
                    if (gi < (8 >> ss)) {
                        int t0 = (gi << (ss + 1)) | q;
                        int t1 = t0 + mloc;
                        float br = vr_[t1], bi = vi_[t1];
                        float pr = br * w.x + bi * w.y;      // conj twiddle
                        float pi = bi * w.x - br * w.y;
                        float ar = vr_[t0], ai = vi_[t0];
                        vr_[t0] = ar + pr;  vi_[t0] = ai + pi;
                        vr_[t1] = ar - pr;  vi_[t1] = ai - pi;
                    }
                }
                float2 wn;                                   // w <- w * ws
                wn.x = w.x * ws.x - w.y * ws.y;
                wn.y = w.x * ws.y + w.y * ws.x;
                w = wn;
            }
        }
    }
}

// ---------------- setup: twiddle table + Wh hi/lo split (one launch) -----------------
__global__ void setup_kernel(const float* __restrict__ Wh_w) {
    int i = blockIdx.x * blockDim.x + threadIdx.x;
    if (i < NH) {
        float s, c;
        sincospif(-(float)i / 4096.0f, &s, &c);
        g_tw[i] = make_float2(c, s);
    }
    if (i < HID * MSZ) bsplit(Wh_w[i], g_Whi[i], g_Wlo[i]);
}

// ---------------- u = relu(x @ Wu^T + b), fused x hi/lo split -------------------------
__global__ void u_kernel(const float* __restrict__ x,
                         const float* __restrict__ Wu_w,
                         const float* __restrict__ Wu_b) {
    int gw   = (blockIdx.x * blockDim.x + threadIdx.x) >> 5;
    int lane = threadIdx.x & 31;
    if (gw >= BATCH * SEQ) return;
    int b = gw >> 12, t = gw & (SEQ - 1);
    size_t rowoff = (size_t)(b * SEQ + t) * INPUT;
    const float* xp = x + rowoff;
    float a0 = 0.f, a1 = 0.f, a2 = 0.f, a3 = 0.f;
    #pragma unroll
    for (int i = lane; i < INPUT; i += 32) {
        float xv = xp[i];
        __nv_bfloat16 hi, lo;
        bsplit(xv, hi, lo);
        g_xhi[rowoff + i] = hi;
        g_xlo[rowoff + i] = lo;
        a0 = fmaf(xv, __ldg(&Wu_w[0 * INPUT + i]), a0);
        a1 = fmaf(xv, __ldg(&Wu_w[1 * INPUT + i]), a1);
        a2 = fmaf(xv, __ldg(&Wu_w[2 * INPUT + i]), a2);
        a3 = fmaf(xv, __ldg(&Wu_w[3 * INPUT + i]), a3);
    }
    #pragma unroll
    for (int off = 16; off; off >>= 1) {
        a0 += __shfl_down_sync(0xffffffffu, a0, off);
        a1 += __shfl_down_sync(0xffffffffu, a1, off);
        a2 += __shfl_down_sync(0xffffffffu, a2, off);
        a3 += __shfl_down_sync(0xffffffffu, a3, off);
    }
    if (lane == 0) {
        g_u[(b * 4 + 0) * SEQ + t] = fmaxf(a0 + Wu_b[0], 0.f);
        g_u[(b * 4 + 1) * SEQ + t] = fmaxf(a1 + Wu_b[1], 0.f);
        g_u[(b * 4 + 2) * SEQ + t] = fmaxf(a2 + Wu_b[2], 0.f);
        g_u[(b * 4 + 3) * SEQ + t] = fmaxf(a3 + Wu_b[3], 0.f);
    }
}

// ---------------- forward real FFT, both inputs in ONE launch -------------------------
__global__ void fft_fwd_kernel(const float* __restrict__ Hin) {
    __shared__ float sre[NH];
    __shared__ float sim[NH];
    int blk = blockIdx.x;
    int mode = (blk >= 32);
    int row = mode ? (blk - 32) : blk;
    int tid = threadIdx.x;
    const float* in = mode ? (Hin + (size_t)row * SEQ) : (g_u + (size_t)row * SEQ);

    const float2* in2 = (const float2*)in;
    #pragma unroll
    for (int r = 0; r < NH / FFT_T; ++r) {
        int n = tid + r * FFT_T;
        if (n < SEQ / 2) { float2 v = in2[n]; sre[n] = v.x; sim[n] = v.y; }
        else             { sre[n] = 0.f;      sim[n] = 0.f; }
    }
    __syncthreads();

    #pragma unroll
    for (int s = LOGH - 2; s >= 0; s -= 2) {
        int m = 1 << s;
        #pragma unroll
        for (int r = 0; r < (NH / 4) / FFT_T; ++r) {
            int k = tid + r * FFT_T;
            int j = k & (m - 1);
            int base = ((k >> s) << (s + 2)) + j;
            int ia = base, ib = base + m, ic = base + 2 * m, id = base + 3 * m;
            float2 w2 = g_tw[j << (LOGH - s - 1)];
            float2 w1 = g_tw[j << (LOGH - s)];
            float ar = sre[ia], ai = sim[ia];
            float br = sre[ib], bi = sim[ib];
            float cr = sre[ic], ci = sim[ic];
            float dr = sre[id], di = sim[id];
            float a1r = ar + cr, a1i = ai + ci;
            float tr  = ar - cr, ti  = ai - ci;
            float c1r = tr * w2.x - ti * w2.y;
            float c1i = tr * w2.y + ti * w2.x;
            float b1r = br + dr, b1i = bi + di;
            tr = br - dr; ti = bi - di;
            float er = tr * w2.x - ti * w2.y;
            float ei = tr * w2.y + ti * w2.x;
            float d1r = ei, d1i = -er;                     // * (-i)
            sre[ia] = a1r + b1r;  sim[ia] = a1i + b1i;
            tr = a1r - b1r; ti = a1i - b1i;
            sre[ib] = tr * w1.x - ti * w1.y;
            sim[ib] = tr * w1.y + ti * w1.x;
            sre[ic] = c1r + d1r;  sim[ic] = c1i + d1i;
            tr = c1r - d1r; ti = c1i - d1i;
            sre[id] = tr * w1.x - ti * w1.y;
            sim[id] = tr * w1.y + ti * w1.x;
        }
        __syncthreads();
    }

    if (mode == 0) {
        float* outre = g_Ure + (size_t)row * KS;
        float* outim = g_Uim + (size_t)row * KS;
        #pragma unroll
        for (int r = 0; r < NH / FFT_T; ++r) {
            int j = tid + r * FFT_T;
            if (j == 0) {
                float zr = sre[0], zi = sim[0];
                outre[0]  = zr + zi;  outim[0]  = 0.f;
                outre[NH] = zr - zi;  outim[NH] = 0.f;
            } else {
                int k = rev12(j);
                int p = rev12(NH - k);
                float zjr = sre[j], zji = sim[j];
                float zpr = sre[p], zpi = sim[p];
                float Ar = 0.5f * (zjr + zpr), Ai = 0.5f * (zji - zpi);
                float Br = 0.5f * (zji + zpi), Bi = -0.5f * (zjr - zpr);
                float2 w = g_tw[k];
                outre[j] = Ar + w.x * Br - w.y * Bi;
                outim[j] = Ai + w.x * Bi + w.y * Br;
            }
        }
    } else {
        size_t off = (size_t)row * KS;
        for (int pcol = NH + 1 + tid; pcol < KS; pcol += FFT_T) {
            g_Hrehi[off + pcol] = __float2bfloat16(0.f);
            g_Hrelo[off + pcol] = __float2bfloat16(0.f);
            g_Himhi[off + pcol] = __float2bfloat16(0.f);
            g_Himlo[off + pcol] = __float2bfloat16(0.f);
        }
        #pragma unroll
        for (int r = 0; r < NH / FFT_T; ++r) {
            int j = tid + r * FFT_T;
            float vre, vim;
            if (j == 0) {
                float zr = sre[0], zi = sim[0];
                vre = zr + zi; vim = 0.f;
                float nre = zr - zi;
                bsplit(nre, g_Hrehi[off + NH], g_Hrelo[off + NH]);
                bsplit(0.f, g_Himhi[off + NH], g_Himlo[off + NH]);
            } else {
                int k = rev12(j);
                int p = rev12(NH - k);
                float zjr = sre[j], zji = sim[j];
                float zpr = sre[p], zpi = sim[p];
                float Ar = 0.5f * (zjr + zpr), Ai = 0.5f * (zji - zpi);
                float Br = 0.5f * (zji + zpi), Bi = -0.5f * (zjr - zpr);
                float2 w = g_tw[k];
                vre = Ar + w.x * Br - w.y * Bi;
                vim = Ai + w.x * Bi + w.y * Br;
            }
            bsplit(vre, g_Hrehi[off + j], g_Hrelo[off + j]);
            bsplit(vim, g_Himhi[off + j], g_Himlo[off + j]);
        }
    }
}

// ---------------- G build: cp.async double-buffered bf16-split GEMM ------------------
struct GBuf {
    __nv_bfloat16 Ahi[64][40], Alo[64][40];          // [m][k]
    __nv_bfloat16 Bhi[2][32][136], Blo[2][32][136];  // [re/im][k][n]
};
#define GB_SMEM ((int)(2 * sizeof(GBuf)))

__device__ __forceinline__ void gbuild_load(GBuf& bb, int d, int h0, int k0, int o0, int tid) {
    {
        int m = tid >> 2, c = (tid & 3) * 8;
        size_t src = (size_t)(h0 + m) * MSZ + d * ORDER + o0 + c;
        cp16(&bb.Ahi[m][c], &g_Whi[src]);
        cp16(&bb.Alo[m][c], &g_Wlo[src]);
    }
    #pragma unroll
    for (int r = 0; r < 2; ++r) {
        int oo = (tid >> 4) + r * 16;
        int c  = (tid & 15) * 8;
        size_t src = (size_t)(o0 + oo) * KS + k0 + c;
        cp16(&bb.Bhi[0][oo][c], &g_Hrehi[src]);
        cp16(&bb.Blo[0][oo][c], &g_Hrelo[src]);
        cp16(&bb.Bhi[1][oo][c], &g_Himhi[src]);
        cp16(&bb.Blo[1][oo][c], &g_Himlo[src]);
    }
}

__global__ __launch_bounds__(256)
void gbuild_bf16_kernel() {
    extern __shared__ char smem_raw[];
    GBuf* bufs = (GBuf*)smem_raw;
    int d  = blockIdx.z;
    int h0 = blockIdx.y * 64;
    int k0 = blockIdx.x * 128;
    int tid = threadIdx.x;
    int w  = tid >> 5;
    int wm = w & 1;
    int wn = w >> 1;

    FC accr[2][2], acci[2][2];
    #pragma unroll
    for (int m2 = 0; m2 < 2; ++m2)
        #pragma unroll
        for (int n2 = 0; n2 < 2; ++n2) {
            wmma::fill_fragment(accr[m2][n2], 0.f);
            wmma::fill_fragment(acci[m2][n2], 0.f);
        }

    gbuild_load(bufs[0], d, h0, k0, 0, tid);
    cp_commit();

    #pragma unroll
    for (int it = 0; it < ORDER / 32; ++it) {
        int cur = it & 1;
        if (it + 1 < ORDER / 32) {
            gbuild_load(bufs[cur ^ 1], d, h0, k0, (it + 1) * 32, tid);
            cp_commit();
            asm volatile("cp.async.wait_group 1;");
        } else {
            asm volatile("cp.async.wait_group 0;");
        }
        __syncthreads();
        GBuf& bb = bufs[cur];
        #pragma unroll
        for (int kk = 0; kk < 32; kk += 16) {
            FA ahi[2], alo[2];
            #pragma unroll
            for (int m2 = 0; m2 < 2; ++m2) {
                wmma::load_matrix_sync(ahi[m2], &bb.Ahi[wm * 32 + m2 * 16][kk], 40);
                wmma::load_matrix_sync(alo[m2], &bb.Alo[wm * 32 + m2 * 16][kk], 40);
            }
            #pragma unroll
            for (int n2 = 0; n2 < 2; ++n2) {
                FBr bhi, blo;
                wmma::load_matrix_sync(bhi, &bb.Bhi[0][kk][wn * 32 + n2 * 16], 136);
                wmma::load_matrix_sync(blo, &bb.Blo[0][kk][wn * 32 + n2 * 16], 136);
                #pragma unroll
                for (int m2 = 0; m2 < 2; ++m2) {
                    wmma::mma_sync(accr[m2][n2], ahi[m2], bhi, accr[m2][n2]);
                    wmma::mma_sync(accr[m2][n2], alo[m2], bhi, accr[m2][n2]);
                    wmma::mma_sync(accr[m2][n2], ahi[m2], blo, accr[m2][n2]);
                }
                wmma::load_matrix_sync(bhi, &bb.Bhi[1][kk][wn * 32 + n2 * 16], 136);
                wmma::load_matrix_sync(blo, &bb.Blo[1][kk][wn * 32 + n2 * 16], 136);
                #pragma unroll
                for (int m2 = 0; m2 < 2; ++m2) {
                    wmma::mma_sync(acci[m2][n2], ahi[m2], bhi, acci[m2][n2]);
                    wmma::mma_sync(acci[m2][n2], alo[m2], bhi, acci[m2][n2]);
                    wmma::mma_sync(acci[m2][n2], ahi[m2], blo, acci[m2][n2]);
                }
            }
        }
        __syncthreads();
    }
    #pragma unroll
    for (int m2 = 0; m2 < 2; ++m2)
        #pragma unroll
        for (int n2 = 0; n2 < 2; ++n2) {
            size_t dst = ((size_t)(h0 + wm * 32 + m2 * 16) * MD + d) * KS
                       + k0 + wn * 32 + n2 * 16;
            wmma::store_matrix_sync(&g_Gre[dst], accr[m2][n2], MD * KS, wmma::mem_row_major);
            wmma::store_matrix_sync(&g_Gim[dst], acci[m2][n2], MD * KS, wmma::mem_row_major);
        }
}

// ---------------- hx GEMM: cp.async double-buffered, 32x32 warp tiles ----------------
struct HBuf {
    __nv_bfloat16 Ahi[64][40], Alo[64][40];    // [h][i]
    __nv_bfloat16 Bhi[128][40], Blo[128][40];  // [t][i]
};
#define HX_SMEM ((int)(2 * sizeof(HBuf)))

__device__ __forceinline__ void hx_load(HBuf& bb, int b, int h0, int t0, int i0, int tid) {
    {
        int m = tid >> 2, c = (tid & 3) * 8;
        size_t src = (size_t)(h0 + m) * MSZ + MD * ORDER + i0 + c;
        cp16(&bb.Ahi[m][c], &g_Whi[src]);
        cp16(&bb.Alo[m][c], &g_Wlo[src]);
    }
    #pragma unroll
    for (int r = 0; r < 2; ++r) {
        int e = tid + r * 256;
        int tt = e >> 2, c = (e & 3) * 8;
        size_t src = (size_t)(b * SEQ + t0 + tt) * INPUT + i0 + c;
        cp16(&bb.Bhi[tt][c], &g_xhi[src]);
        cp16(&bb.Blo[tt][c], &g_xlo[src]);
    }
}

__global__ __launch_bounds__(256)
void hx_bf16_kernel(const float* __restrict__ Wh_b) {
    extern __shared__ char smem_raw[];
    HBuf* bufs = (HBuf*)smem_raw;
    __shared__ float sBias[64][16];
    int b  = blockIdx.z;
    int h0 = blockIdx.y * 64;
    int t0 = blockIdx.x * 128;
    int tid = threadIdx.x;
    int w  = tid >> 5;
    int wm = w & 1;
    int wn = w >> 1;

    #pragma unroll
    for (int r = 0; r < 4; ++r) {
        int e = tid + r * 256;
        sBias[e >> 4][e & 15] = Wh_b[h0 + (e >> 4)];
    }

    hx_load(bufs[0], b, h0, t0, 0, tid);
    cp_commit();
    __syncthreads();   // sBias ready

    FC acc[2][2];
    #pragma unroll
    for (int m2 = 0; m2 < 2; ++m2)
        #pragma unroll
        for (int n2 = 0; n2 < 2; ++n2)
            wmma::load_matrix_sync(acc[m2][n2], &sBias[wm * 32 + m2 * 16][0], 16,
                                   wmma::mem_row_major);

    #pragma unroll
    for (int it = 0; it < INPUT / 32; ++it) {
        int cur = it & 1;
        if (it + 1 < INPUT / 32) {
            hx_load(bufs[cur ^ 1], b, h0, t0, (it + 1) * 32, tid);
            cp_commit();
            asm volatile("cp.async.wait_group 1;");
        } else {
            asm volatile("cp.async.wait_group 0;");
        }
        __syncthreads();
        HBuf& bb = bufs[cur];
        #pragma unroll
        for (int kk = 0; kk < 32; kk += 16) {
            FA ahi[2], alo[2];
            #pragma unroll
            for (int m2 = 0; m2 < 2; ++m2) {
                wmma::load_matrix_sync(ahi[m2], &bb.Ahi[wm * 32 + m2 * 16][kk], 40);
                wmma::load_matrix_sync(alo[m2], &bb.Alo[wm * 32 + m2 * 16][kk], 40);
            }
            #pragma unroll
            for (int n2 = 0; n2 < 2; ++n2) {
                FBc bhi, blo;
                wmma::load_matrix_sync(bhi, &bb.Bhi[wn * 32 + n2 * 16][kk], 40);
                wmma::load_matrix_sync(blo, &bb.Blo[wn * 32 + n2 * 16][kk], 40);
                #pragma unroll
                for (int m2 = 0; m2 < 2; ++m2) {
                    wmma::mma_sync(acc[m2][n2], ahi[m2], bhi, acc[m2][n2]);
                    wmma::mma_sync(acc[m2][n2], alo[m2], bhi, acc[m2][n2]);
                    wmma::mma_sync(acc[m2][n2], ahi[m2], blo, acc[m2][n2]);
                }
            }
        }
        __syncthreads();
    }
    #pragma unroll
    for (int m2 = 0; m2 < 2; ++m2)
        #pragma unroll
        for (int n2 = 0; n2 < 2; ++n2) {
            size_t dst = ((size_t)b * HID + h0 + wm * 32 + m2 * 16) * SEQ
                       + t0 + wn * 32 + n2 * 16;
            wmma::store_matrix_sync(&g_hx[dst], acc[m2][n2], SEQ, wmma::mem_row_major);
        }
}

// ---------------- P = sum_d G*U ; real-iFFT (3x radix-16 reg passes, 2 batches) ------
__global__ __launch_bounds__(FFT_T, 2)
void pifft_kernel() {
    __shared__ float sre[2][SMSZ];
    __shared__ float sim[2][SMSZ];
    __shared__ float s_nyq[2];
    int h  = blockIdx.x >> 2;
    int bp = blockIdx.x & 3;
    int b0 = bp * 2;
    int tid = threadIdx.x;

    const float* Ur0 = g_Ure + (size_t)b0 * MD * KS;
    const float* Ui0 = g_Uim + (size_t)b0 * MD * KS;
    const float* Ur1 = Ur0 + MD * KS;
    const float* Ui1 = Ui0 + MD * KS;
    const float* Gr  = g_Gre + (size_t)h * MD * KS;
    const float* Gi  = g_Gim + (size_t)h * MD * KS;

    #pragma unroll
    for (int r = 0; r < NH / (FFT_T * 2); ++r) {
        int j = tid * 2 + r * (FFT_T * 2);
        float pr0a = 0.f, pi0a = 0.f, pr1a = 0.f, pi1a = 0.f;
        float pr0b = 0.f, pi0b = 0.f, pr1b = 0.f, pi1b = 0.f;
        #pragma unroll
        for (int d = 0; d < MD; ++d) {
            float2 gr = *(const float2*)&Gr [d * KS + j];
            float2 gi = *(const float2*)&Gi [d * KS + j];
            float2 ar = *(const float2*)&Ur0[d * KS + j];
            float2 ai = *(const float2*)&Ui0[d * KS + j];
            float2 br = *(const float2*)&Ur1[d * KS + j];
            float2 bi = *(const float2*)&Ui1[d * KS + j];
            pr0a += ar.x * gr.x - ai.x * gi.x;
            pi0a += ar.x * gi.x + ai.x * gr.x;
            pr1a += br.x * gr.x - bi.x * gi.x;
            pi1a += br.x * gi.x + bi.x * gr.x;
            pr0b += ar.y * gr.y - ai.y * gi.y;
            pi0b += ar.y * gi.y + ai.y * gr.y;
            pr1b += br.y * gr.y - bi.y * gi.y;
            pi1b += br.y * gi.y + bi.y * gr.y;
        }
        int pj = PH(j);
        sre[0][pj] = pr0a; sim[0][pj] = pi0a;
        sre[1][pj] = pr1a; sim[1][pj] = pi1a;
        int pj1 = PH(j + 1);
        sre[0][pj1] = pr0b; sim[0][pj1] = pi0b;
        sre[1][pj1] = pr1b; sim[1][pj1] = pi1b;
    }
    if (tid < 2) {
        const float* Urb = tid ? Ur1 : Ur0;
        const float* Uib = tid ? Ui1 : Ui0;
        float pn = 0.f;
        #pragma unroll
        for (int d = 0; d < MD; ++d)
            pn += Urb[d * KS + NH] * Gr[d * KS + NH] - Uib[d * KS + NH] * Gi[d * KS + NH];
        s_nyq[tid] = pn;
    }
    __syncthreads();

    // IN-PLACE pair untangle: even bitrev slot j (spectral k<2048) owns its
    // Hermitian partner p (odd slot). Z[p] = (Xer+Xoi, Xor-Xei) by symmetry.
    #pragma unroll
    for (int r = 0; r < NH / (FFT_T * 2); ++r) {
        int j = (tid + r * FFT_T) * 2;
        if (j == 0) {
            #pragma unroll
            for (int q = 0; q < 2; ++q) {
                float p0 = sre[q][PH(0)], pn = s_nyq[q];
                sre[q][PH(0)] = 0.5f * (p0 + pn);
                sim[q][PH(0)] = 0.5f * (p0 - pn);
                // slot 1 = spectral k = 2048, self-paired: Z = (re, -im)
                sim[q][PH(1)] = -sim[q][PH(1)];
            }
        } else {
            int k = rev12(j);                 // 1..2047 (j even)
            int p = rev12(NH - k);            // odd slot, unique
            int pj = PH(j), pp = PH(p);
            float2 w = g_tw[k];
            #pragma unroll
            for (int q = 0; q < 2; ++q) {
                float pjr = sre[q][pj], pji = sim[q][pj];
                float ppr = sre[q][pp], ppi = sim[q][pp];
                float Xer = 0.5f * (pjr + ppr), Xei = 0.5f * (pji - ppi);
                float Dr  = 0.5f * (pjr - ppr), Di  = 0.5f * (pji + ppi);
                float Xor = w.x * Dr + w.y * Di;
                float Xoi = w.x * Di - w.y * Dr;
                sre[q][pj] = Xer - Xoi;  sim[q][pj] = Xei + Xor;
                sre[q][pp] = Xer + Xoi;  sim[q][pp] = Xor - Xei;
            }
        }
    }
    __syncthreads();

    {
        int q = tid >> 8;
        int g = tid & 255;
        float* qre = sre[q];
        float* qim = sim[q];
        float vr_[16], vi_[16];
        {
            int pb = PH(g << 4);
            #pragma unroll
            for (int t = 0; t < 16; ++t) { vr_[t] = qre[pb + t]; vi_[t] = qim[pb + t]; }
            fft16_dit<12>(vr_, vi_, 0, 1);
            #pragma unroll
            for (int t = 0; t < 16; ++t) { qre[pb + t] = vr_[t]; qim[pb + t] = vi_[t]; }
        }
        __syncthreads();
        {
            int base = ((g >> 4) << 8) + (g & 15);
            #pragma unroll
            for (int t = 0; t < 16; ++t) {
                int p = PH(base + (t << 4));
                vr_[t] = qre[p]; vi_[t] = qim[p];
            }
            fft16_dit<8>(vr_, vi_, g & 15, 16);
            #pragma unroll
            for (int t = 0; t < 16; ++t) {
                int p = PH(base + (t << 4));
                qre[p] = vr_[t]; qim[p] = vi_[t];
            }
        }
        __syncthreads();
        {
            #pragma unroll
            for (int t = 0; t < 16; ++t) {
                int p = PH(g + (t << 8));
                vr_[t] = qre[p]; vi_[t] = qim[p];
            }
            fft16_dit<4>(vr_, vi_, g, 256);
            #pragma unroll
            for (int t = 0; t < 16; ++t) {
                int p = PH(g + (t << 8));
                qre[p] = vr_[t]; qim[p] = vi_[t];
            }
        }
    }
    __syncthreads();

    const float inv_n = 1.0f / 4096.0f;
    #pragma unroll
    for (int q = 0; q < 2; ++q) {
        float2* hx2 = (float2*)(g_hx + (size_t)((b0 + q) * HID + h) * SEQ);
        #pragma unroll
        for (int r = 0; r < (SEQ / 2) / FFT_T; ++r) {
            int n = tid + r * FFT_T;
            int pn = PH(n);
            float2 old = hx2[n];
            float2 v;
            v.x = fmaxf(fmaf(sre[q][pn], inv_n, old.x), 0.f);
            v.y = fmaxf(fmaf(sim[q][pn], inv_n, old.y), 0.f);
            hx2[n] = v;
        }
    }
}

// ---------------- transpose [b][h][t] -> out [b][t][h] (float4 loads) ----------------
__global__ void fuse_kernel(float* __restrict__ out) {
    __shared__ float tile[32][133];
    int b  = blockIdx.z;
    int h0 = blockIdx.y * 32;
    int t0 = blockIdx.x * 128;
    int tid = threadIdx.y * 32 + threadIdx.x;

    #pragma unroll
    for (int r = 0; r < 4; ++r) {
        int e  = tid + r * 256;
        int hh = e >> 5;
        int qt = (e & 31) * 4;
        float4 v = *(const float4*)&g_hx[(size_t)(b * HID + h0 + hh) * SEQ + t0 + qt];
        tile[hh][qt + 0] = v.x;
        tile[hh][qt + 1] = v.y;
        tile[hh][qt + 2] = v.z;
        tile[hh][qt + 3] = v.w;
    }
    __syncthreads();

    int lane = tid & 31;
    int wrp  = tid >> 5;
    #pragma unroll
    for (int r = 0; r < 16; ++r) {
        int tloc = wrp + r * 8;
        out[(size_t)(b * SEQ + t0 + tloc) * HID + h0 + lane] = tile[lane][tloc];
    }
}

// ---------------- h[:, -1, :] appended after h ----------------------------------------
__global__ void last_kernel(float* __restrict__ out) {
    int i = blockIdx.x * blockDim.x + threadIdx.x;
    if (i < BATCH * HID)
        out[(size_t)BATCH * SEQ * HID + i] = g_hx[(size_t)i * SEQ + (SEQ - 1)];
}

// ---------------- launch ---------------------------------------------------------------
extern "C" void kernel_launch(void* const* d_in, const int* in_sizes, int n_in,
                              void* d_out, int out_size) {
    const float* x    = (const float*)d_in[0];
    const float* Wu_w = (const float*)d_in[1];
    const float* Wu_b = (const float*)d_in[2];
    const float* Wh_w = (const float*)d_in[3];
    const float* Wh_b = (const float*)d_in[4];
    const float* H    = (const float*)d_in[5];
    float* out = (float*)d_out;

    static int configured = 0;
    if (!configured) {
        cudaFuncSetAttribute(gbuild_bf16_kernel,
                             cudaFuncAttributeMaxDynamicSharedMemorySize, GB_SMEM);
        cudaFuncSetAttribute(hx_bf16_kernel,
                             cudaFuncAttributeMaxDynamicSharedMemorySize, HX_SMEM);
        configured = 1;
    }

    setup_kernel<<<(HID * MSZ + 511) / 512, 512>>>(Wh_w);
    u_kernel<<<(BATCH * SEQ * 32) / 256, 256>>>(x, Wu_w, Wu_b);

    fft_fwd_kernel<<<32 + ORDER, FFT_T>>>(H);      // u + H spectra, one launch

    gbuild_bf16_kernel<<<dim3(KS / 128, HID / 64, MD), 256, GB_SMEM>>>();
    hx_bf16_kernel<<<dim3(SEQ / 128, HID / 64, BATCH), 256, HX_SMEM>>>(Wh_b);

    pifft_kernel<<<HID * BATCH / 2, FFT_T>>>();

    fuse_kernel<<<dim3(SEQ / 128, HID / 32, BATCH), dim3(32, 8)>>>(out);
    if (out_size >= BATCH * SEQ * HID + BATCH * HID)
        last_kernel<<<8, 512>>>(out);
}